// round 14
// baseline (speedup 1.0000x reference)
#include <cuda_runtime.h>
#include <cuda_bf16.h>
#include <math.h>
#include <stdint.h>

#define DIM     1024
#define HEADS   16
#define DHEAD   64
#define INNER   1024
#define BATCH   4
#define NTOK    4096
#define MTOT    (BATCH * NTOK)      // 16384
#define QKVN    (3 * INNER)         // 3072

// ---------------------------------------------------------------------------
// Scratch (device globals)
// ---------------------------------------------------------------------------
__device__ float g_q[(size_t)MTOT * INNER];
__device__ float g_T[(size_t)BATCH * DIM * INNER];
__device__ float g_C[(size_t)BATCH * HEADS * DHEAD * DHEAD];

__device__ __nv_bfloat16 g_xh[(size_t)MTOT * DIM];
__device__ __nv_bfloat16 g_xl[(size_t)MTOT * DIM];
__device__ __nv_bfloat16 g_xth[(size_t)BATCH * DIM * NTOK];
__device__ __nv_bfloat16 g_xtl[(size_t)BATCH * DIM * NTOK];
__device__ __nv_bfloat16 g_uh[(size_t)MTOT * DIM];
__device__ __nv_bfloat16 g_ul[(size_t)MTOT * DIM];
__device__ __nv_bfloat16 g_wqh[(size_t)INNER * DIM];
__device__ __nv_bfloat16 g_wql[(size_t)INNER * DIM];
__device__ __nv_bfloat16 g_wvh[(size_t)INNER * DIM];
__device__ __nv_bfloat16 g_wvl[(size_t)INNER * DIM];
__device__ __nv_bfloat16 g_woh[(size_t)INNER * DIM];
__device__ __nv_bfloat16 g_wol[(size_t)INNER * DIM];
__device__ __nv_bfloat16 g_Gh[(size_t)BATCH * DIM * DIM];
__device__ __nv_bfloat16 g_Gl[(size_t)BATCH * DIM * DIM];

// ---------------------------------------------------------------------------
// helpers
// ---------------------------------------------------------------------------
__device__ __forceinline__ uint32_t smem_u32(const void* p) {
    uint32_t a;
    asm("{ .reg .u64 t; cvta.to.shared.u64 t, %1; cvt.u32.u64 %0, t; }"
        : "=r"(a) : "l"(p));
    return a;
}
__device__ __forceinline__ void cp_async16(uint32_t dst, const void* src) {
    asm volatile("cp.async.cg.shared.global [%0], [%1], 16;"
                 :: "r"(dst), "l"(src) : "memory");
}
__device__ __forceinline__ void cp_commit() {
    asm volatile("cp.async.commit_group;" ::: "memory");
}
template <int N>
__device__ __forceinline__ void cp_wait() {
    asm volatile("cp.async.wait_group %0;" :: "n"(N) : "memory");
}
__device__ __forceinline__ void ldm_x4(uint32_t& r0, uint32_t& r1,
                                       uint32_t& r2, uint32_t& r3, uint32_t a) {
    asm volatile("ldmatrix.sync.aligned.m8n8.x4.shared.b16 {%0,%1,%2,%3}, [%4];"
                 : "=r"(r0), "=r"(r1), "=r"(r2), "=r"(r3) : "r"(a));
}
__device__ __forceinline__ void mma_bf16(float& c0, float& c1, float& c2, float& c3,
                                         uint32_t a0, uint32_t a1, uint32_t a2, uint32_t a3,
                                         uint32_t b0, uint32_t b1) {
    asm volatile(
        "mma.sync.aligned.m16n8k16.row.col.f32.bf16.bf16.f32 "
        "{%0,%1,%2,%3}, {%4,%5,%6,%7}, {%8,%9}, {%0,%1,%2,%3};"
        : "+f"(c0), "+f"(c1), "+f"(c2), "+f"(c3)
        : "r"(a0), "r"(a1), "r"(a2), "r"(a3), "r"(b0), "r"(b1));
}
__device__ __forceinline__ void split_bf16(float f, ushort& h, ushort& l) {
    __nv_bfloat16 hi = __float2bfloat16(f);
    __nv_bfloat16 lo = __float2bfloat16(f - __bfloat162float(hi));
    h = __bfloat16_as_ushort(hi);
    l = __bfloat16_as_ushort(lo);
}

// ---------------------------------------------------------------------------
// New GEMM: CTA tile 256x128, BK=32, 8 warps (4m x 2n), warp tile 64x64.
// 1 CTA/SM, ~120KB smem double-buffered.
// ---------------------------------------------------------------------------
#define BKC      32
#define ROWB     80
#define A_BYTES  (256 * ROWB)            // 20480
#define B_BYTES  (128 * ROWB)            // 10240
#define BUFSZ2   (2 * A_BYTES + 2 * B_BYTES)  // 61440
#define GEMM_SMEM2 (2 * BUFSZ2)          // 122880

// mainloop: leaves results in acc[4][8][4]
#define GEMM_MAINLOOP2(Ah_, Al_, Bth_, Btl_, K_)                               \
    const uint32_t sb = smem_u32(smem);                                        \
    const int tid = threadIdx.x;                                               \
    const int lane = tid & 31;                                                 \
    const int wid = tid >> 5;                                                  \
    const int wm = wid & 3;                                                    \
    const int wn = wid >> 2;                                                   \
    const __nv_bfloat16* Apt_h = (Ah_)  + (size_t)mtile * 256 * (K_);          \
    const __nv_bfloat16* Apt_l = (Al_)  + (size_t)mtile * 256 * (K_);          \
    const __nv_bfloat16* Bpt_h = (Bth_) + (size_t)ntile * 128 * (K_);          \
    const __nv_bfloat16* Bpt_l = (Btl_) + (size_t)ntile * 128 * (K_);          \
    const int nchunks = (K_) / BKC;                                            \
    auto issue_chunk = [&](int c, int buf) {                                   \
        const uint32_t db = sb + buf * BUFSZ2;                                 \
        _Pragma("unroll")                                                      \
        for (int j = 0; j < 12; j++) {                                         \
            int f = tid + 256 * j;                                             \
            const __nv_bfloat16* src;                                          \
            uint32_t dst;                                                      \
            if (f < 1024) {                                                    \
                int r = f >> 2, s = f & 3;                                     \
                src = Apt_h + (size_t)r * (K_) + c * BKC + s * 8;              \
                dst = db + r * ROWB + s * 16;                                  \
            } else if (f < 2048) {                                             \
                int i2 = f - 1024; int r = i2 >> 2, s = i2 & 3;                \
                src = Apt_l + (size_t)r * (K_) + c * BKC + s * 8;              \
                dst = db + A_BYTES + r * ROWB + s * 16;                        \
            } else if (f < 2560) {                                             \
                int i2 = f - 2048; int r = i2 >> 2, s = i2 & 3;                \
                src = Bpt_h + (size_t)r * (K_) + c * BKC + s * 8;              \
                dst = db + 2 * A_BYTES + r * ROWB + s * 16;                    \
            } else {                                                           \
                int i2 = f - 2560; int r = i2 >> 2, s = i2 & 3;                \
                src = Bpt_l + (size_t)r * (K_) + c * BKC + s * 8;              \
                dst = db + 2 * A_BYTES + B_BYTES + r * ROWB + s * 16;          \
            }                                                                  \
            cp_async16(dst, src);                                              \
        }                                                                      \
        cp_commit();                                                           \
    };                                                                         \
    float acc[4][8][4];                                                        \
    _Pragma("unroll")                                                          \
    for (int im = 0; im < 4; im++)                                             \
        _Pragma("unroll")                                                      \
        for (int jn = 0; jn < 8; jn++)                                         \
            _Pragma("unroll")                                                  \
            for (int r = 0; r < 4; r++) acc[im][jn][r] = 0.f;                  \
    const int at_tile = lane >> 3;                                             \
    const int a_row = (at_tile & 1) * 8 + (lane & 7);                          \
    const int a_cadd = (at_tile >> 1) * 16;                                    \
    const int b_row = ((at_tile >> 1) * 8) + (lane & 7);                       \
    const int b_cadd = (at_tile & 1) * 16;                                     \
    issue_chunk(0, 0);                                                         \
    for (int c = 0; c < nchunks; c++) {                                        \
        const int buf = c & 1;                                                 \
        cp_wait<0>();                                                          \
        __syncthreads();                                                       \
        if (c + 1 < nchunks) issue_chunk(c + 1, buf ^ 1);                      \
        const uint32_t base = sb + buf * BUFSZ2;                               \
        _Pragma("unroll")                                                      \
        for (int kk = 0; kk < 2; kk++) {                                       \
            const int kb = kk * 32;                                            \
            uint32_t ah[4][4], al[4][4];                                       \
            _Pragma("unroll")                                                  \
            for (int im = 0; im < 4; im++) {                                   \
                uint32_t aoff = (uint32_t)(wm * 64 + im * 16 + a_row) * ROWB + kb + a_cadd; \
                ldm_x4(ah[im][0], ah[im][1], ah[im][2], ah[im][3], base + aoff);            \
                ldm_x4(al[im][0], al[im][1], al[im][2], al[im][3], base + A_BYTES + aoff);  \
            }                                                                  \
            _Pragma("unroll")                                                  \
            for (int p = 0; p < 4; p++) {                                      \
                uint32_t bh4[4], bl4[4];                                       \
                uint32_t boff = (uint32_t)(wn * 64 + p * 16 + b_row) * ROWB + kb + b_cadd;  \
                ldm_x4(bh4[0], bh4[1], bh4[2], bh4[3], base + 2 * A_BYTES + boff);          \
                ldm_x4(bl4[0], bl4[1], bl4[2], bl4[3], base + 2 * A_BYTES + B_BYTES + boff);\
                _Pragma("unroll")                                              \
                for (int im = 0; im < 4; im++) {                               \
                    _Pragma("unroll")                                          \
                    for (int q2 = 0; q2 < 2; q2++) {                           \
                        const int jn = p * 2 + q2;                             \
                        const int q = q2 * 2;                                  \
                        float* cc = acc[im][jn];                               \
                        mma_bf16(cc[0], cc[1], cc[2], cc[3],                   \
                                 ah[im][0], ah[im][1], ah[im][2], ah[im][3],   \
                                 bh4[q], bh4[q + 1]);                          \
                        mma_bf16(cc[0], cc[1], cc[2], cc[3],                   \
                                 ah[im][0], ah[im][1], ah[im][2], ah[im][3],   \
                                 bl4[q], bl4[q + 1]);                          \
                        mma_bf16(cc[0], cc[1], cc[2], cc[3],                   \
                                 al[im][0], al[im][1], al[im][2], al[im][3],   \
                                 bh4[q], bh4[q + 1]);                          \
                    }                                                          \
                }                                                              \
            }                                                                  \
        }                                                                      \
    }

// fp32 epilogue (optional bias)
__device__ __forceinline__ void gemm_f32_body(
    char* smem, int mtile, int ntile,
    const __nv_bfloat16* __restrict__ Ah, const __nv_bfloat16* __restrict__ Al,
    const __nv_bfloat16* __restrict__ Bth, const __nv_bfloat16* __restrict__ Btl,
    float* __restrict__ C, const float* __restrict__ bias, int N, int K)
{
    GEMM_MAINLOOP2(Ah, Al, Bth, Btl, K)
    const int m0 = mtile * 256 + wm * 64;
    const int n0 = ntile * 128 + wn * 64;
#pragma unroll
    for (int im = 0; im < 4; im++) {
#pragma unroll
        for (int jn = 0; jn < 8; jn++) {
            const int row = m0 + im * 16 + (lane >> 2);
            const int col = n0 + jn * 8 + (lane & 3) * 2;
            float b0 = bias ? bias[col] : 0.f;
            float b1 = bias ? bias[col + 1] : 0.f;
            float2 v0 = {acc[im][jn][0] + b0, acc[im][jn][1] + b1};
            float2 v1 = {acc[im][jn][2] + b0, acc[im][jn][3] + b1};
            *reinterpret_cast<float2*>(C + (size_t)row * N + col) = v0;
            *reinterpret_cast<float2*>(C + (size_t)(row + 8) * N + col) = v1;
        }
    }
}

// G epilogue: write bf16 h/l (full matrix, no mirroring)
__device__ __forceinline__ void gemm_G_body(char* smem, int batch, int mtile, int ntile)
{
    const __nv_bfloat16* Ab = g_xth + (size_t)batch * DIM * NTOK;
    const __nv_bfloat16* Al_ = g_xtl + (size_t)batch * DIM * NTOK;
    GEMM_MAINLOOP2(Ab, Al_, Ab, Al_, NTOK)
    const int m0 = mtile * 256 + wm * 64;
    const int n0 = ntile * 128 + wn * 64;
    __nv_bfloat16* GH = g_Gh + (size_t)batch * DIM * DIM;
    __nv_bfloat16* GL = g_Gl + (size_t)batch * DIM * DIM;
#pragma unroll
    for (int im = 0; im < 4; im++) {
#pragma unroll
        for (int jn = 0; jn < 8; jn++) {
            const int row = m0 + im * 16 + (lane >> 2);
            const int col = n0 + jn * 8 + (lane & 3) * 2;
            ushort h0, l0, h1, l1, h2, l2, h3, l3;
            split_bf16(acc[im][jn][0], h0, l0);
            split_bf16(acc[im][jn][1], h1, l1);
            split_bf16(acc[im][jn][2], h2, l2);
            split_bf16(acc[im][jn][3], h3, l3);
            *reinterpret_cast<uint32_t*>(GH + (size_t)row * DIM + col) =
                (uint32_t)h0 | ((uint32_t)h1 << 16);
            *reinterpret_cast<uint32_t*>(GL + (size_t)row * DIM + col) =
                (uint32_t)l0 | ((uint32_t)l1 << 16);
            *reinterpret_cast<uint32_t*>(GH + (size_t)(row + 8) * DIM + col) =
                (uint32_t)h2 | ((uint32_t)h3 << 16);
            *reinterpret_cast<uint32_t*>(GL + (size_t)(row + 8) * DIM + col) =
                (uint32_t)l2 | ((uint32_t)l3 << 16);
        }
    }
}

// Kernel A: G (128 blocks, 4x work, first) + q-GEMM (512 blocks)
__global__ __launch_bounds__(256, 1) void kernelA2()
{
    extern __shared__ char smem[];
    const int bx = blockIdx.x;
    if (bx < 128) {
        const int batch = bx >> 5, r = bx & 31;
        gemm_G_body(smem, batch, r >> 3, r & 7);
    } else {
        const int i = bx - 128;
        gemm_f32_body(smem, i >> 3, i & 7, g_xh, g_xl, g_wqh, g_wql,
                      g_q, nullptr, INNER, DIM);
    }
}

// T = G @ Wv per batch (128 blocks)
__global__ __launch_bounds__(256, 1) void kernelT()
{
    extern __shared__ char smem[];
    const int bx = blockIdx.x;
    const int batch = bx >> 5, r = bx & 31;
    gemm_f32_body(smem, r >> 3, r & 7,
                  g_Gh + (size_t)batch * DIM * DIM, g_Gl + (size_t)batch * DIM * DIM,
                  g_wvh, g_wvl,
                  g_T + (size_t)batch * DIM * INNER, nullptr, INNER, DIM);
}

// out = u @ Wo + b (512 blocks)
__global__ __launch_bounds__(256, 1) void kernelO(float* __restrict__ out,
                                                  const float* __restrict__ b_o)
{
    extern __shared__ char smem[];
    gemm_f32_body(smem, blockIdx.y, blockIdx.x, g_uh, g_ul, g_woh, g_wol,
                  out, b_o, INNER, DIM);
}

// ---------------------------------------------------------------------------
// Stage-1 packs (unchanged)
// ---------------------------------------------------------------------------
__device__ __forceinline__ void packbt_g(
    float (*tile)[33], const float* __restrict__ W, int ldW, int col0,
    __nv_bfloat16* __restrict__ H, __nv_bfloat16* __restrict__ L,
    size_t outbase, int Kout, int kt, int nt)
{
    const int k0 = kt * 32, n0 = nt * 32;
    const int x = threadIdx.x & 31, y = threadIdx.x >> 5;

#pragma unroll
    for (int r = 0; r < 4; r++) {
        int row = y + r * 8;
        tile[row][x] = W[(size_t)(k0 + row) * ldW + col0 + n0 + x];
    }
    __syncthreads();
#pragma unroll
    for (int r = 0; r < 4; r++) {
        int n = y + r * 8;
        float f = tile[x][n];
        ushort h, l;
        split_bf16(f, h, l);
        size_t o = outbase + (size_t)(n0 + n) * Kout + k0 + x;
        H[o] = __ushort_as_bfloat16(h);
        L[o] = __ushort_as_bfloat16(l);
    }
}

__global__ __launch_bounds__(256) void pack_stage1(
    const float* __restrict__ x, const float* __restrict__ W_qkv,
    const float* __restrict__ W_o)
{
    __shared__ float tile[32][33];
    const int bx = blockIdx.x;
    if (bx < 8192) {
        const size_t e0 = ((size_t)bx * 256 + threadIdx.x) * 8;
        float4 v0 = *reinterpret_cast<const float4*>(x + e0);
        float4 v1 = *reinterpret_cast<const float4*>(x + e0 + 4);
        float f[8] = {v0.x, v0.y, v0.z, v0.w, v1.x, v1.y, v1.z, v1.w};
        ushort h[8], l[8];
#pragma unroll
        for (int i = 0; i < 8; i++) split_bf16(f[i], h[i], l[i]);
        *reinterpret_cast<uint4*>(g_xh + e0) = *reinterpret_cast<uint4*>(h);
        *reinterpret_cast<uint4*>(g_xl + e0) = *reinterpret_cast<uint4*>(l);
    } else if (bx < 24576) {
        const int i = bx - 8192;
        const int batch = i >> 12;
        const int t = i & 4095;
        const int kt = t & 127, nt = t >> 7;
        packbt_g(tile, x + (size_t)batch * NTOK * DIM, DIM, 0,
                 g_xth, g_xtl, (size_t)batch * DIM * NTOK, NTOK, kt, nt);
    } else if (bx < 25600) {
        const int t = bx - 24576;
        packbt_g(tile, W_qkv, QKVN, 0, g_wqh, g_wql, 0, DIM, t & 31, t >> 5);
    } else if (bx < 26624) {
        const int t = bx - 25600;
        packbt_g(tile, W_qkv, QKVN, 2 * INNER, g_wvh, g_wvl, 0, DIM, t & 31, t >> 5);
    } else {
        const int t = bx - 26624;
        packbt_g(tile, W_o, INNER, 0, g_woh, g_wol, 0, DIM, t & 31, t >> 5);
    }
}

// ---------------------------------------------------------------------------
// finalize: kv_bh = Wk_h^T @ T_bh (fp32), row-normalize * gamma^2 -> C
// ---------------------------------------------------------------------------
#define FCH 16

__global__ __launch_bounds__(256) void kv_finalize_kernel(
    const float* __restrict__ W_qkv, const float* __restrict__ gamma)
{
    const int bh = blockIdx.x;
    const int b = bh >> 4, h = bh & 15;

    __shared__ float wks[2][FCH][DHEAD];
    __shared__ float ts[2][FCH][DHEAD];
    __shared__ float red[64][17];
    __shared__ float inv[64];

    const int tid = threadIdx.x;
    const int tx = tid % 16, ty = tid / 16;
    const int lr = tid >> 4, lc = (tid * 4) & 63;

    const uint32_t wk_a[2] = {smem_u32(&wks[0][lr][lc]), smem_u32(&wks[1][lr][lc])};
    const uint32_t ts_a[2] = {smem_u32(&ts[0][lr][lc]), smem_u32(&ts[1][lr][lc])};

    auto issue = [&](int s, int buf) {
        const float* wp = W_qkv + (size_t)(s * FCH + lr) * QKVN + INNER + h * DHEAD + lc;
        const float* tp = g_T + ((size_t)b * DIM + s * FCH + lr) * INNER + h * DHEAD + lc;
        cp_async16(wk_a[buf], wp);
        cp_async16(ts_a[buf], tp);
        cp_commit();
    };

    float acc[4][4];
#pragma unroll
    for (int i = 0; i < 4; i++)
#pragma unroll
        for (int j = 0; j < 4; j++) acc[i][j] = 0.f;

    const int nst = DIM / FCH;
    issue(0, 0);
    for (int s = 0; s < nst; s++) {
        const int buf = s & 1;
        if (s + 1 < nst) { issue(s + 1, buf ^ 1); cp_wait<1>(); }
        else             { cp_wait<0>(); }
        __syncthreads();
#pragma unroll
        for (int nn = 0; nn < FCH; nn++) {
            float rk[4], rv[4];
#pragma unroll
            for (int i = 0; i < 4; i++) rk[i] = wks[buf][nn][ty * 4 + i];
#pragma unroll
            for (int j = 0; j < 4; j++) rv[j] = ts[buf][nn][tx * 4 + j];
#pragma unroll
            for (int i = 0; i < 4; i++)
#pragma unroll
                for (int j = 0; j < 4; j++)
                    acc[i][j] += rk[i] * rv[j];
        }
        __syncthreads();
    }

#pragma unroll
    for (int i = 0; i < 4; i++)
        red[ty * 4 + i][tx] = acc[i][0] * acc[i][0] + acc[i][1] * acc[i][1] +
                              acc[i][2] * acc[i][2] + acc[i][3] * acc[i][3];
    __syncthreads();
    if (tid < 64) {
        float s = 0.f;
#pragma unroll
        for (int t = 0; t < 16; t++) s += red[tid][t];
        const float gm = gamma[h];
        inv[tid] = gm * gm / sqrtf(s);
    }
    __syncthreads();

    float* out = g_C + (size_t)bh * DHEAD * DHEAD;
#pragma unroll
    for (int i = 0; i < 4; i++) {
        const float sc = inv[ty * 4 + i];
#pragma unroll
        for (int j = 0; j < 4; j++)
            out[(ty * 4 + i) * DHEAD + tx * 4 + j] = acc[i][j] * sc;
    }
}

// ---------------------------------------------------------------------------
// apply: u = (q @ C) / ||q||, emits bf16 hi/lo
// ---------------------------------------------------------------------------
#define QPAD 68

__global__ __launch_bounds__(256) void apply_kernel(
    __nv_bfloat16* __restrict__ UH, __nv_bfloat16* __restrict__ UL)
{
    const int bh = blockIdx.x;
    const int chunk = blockIdx.y;
    const int b = bh / HEADS, h = bh % HEADS;

    __shared__ float Cs[DHEAD][DHEAD];
    __shared__ float qs[64][QPAD];
    __shared__ float inv[64];

    const int tid = threadIdx.x;
    const int n0 = chunk * 64;

#pragma unroll
    for (int i = tid * 4; i < DHEAD * DHEAD; i += 1024)
        *reinterpret_cast<float4*>(&Cs[0][0] + i) =
            *reinterpret_cast<const float4*>(g_C + (size_t)bh * DHEAD * DHEAD + i);

#pragma unroll
    for (int i = tid * 4; i < 64 * DHEAD; i += 1024) {
        int t = i / DHEAD, d = i % DHEAD;
        *reinterpret_cast<float4*>(&qs[t][d]) =
            *reinterpret_cast<const float4*>(g_q + (size_t)(b * NTOK + n0 + t) * INNER + h * DHEAD + d);
    }
    __syncthreads();

    if (tid < 64) {
        float ss = 0.f;
#pragma unroll
        for (int d = 0; d < DHEAD; d++) { float v = qs[tid][d]; ss += v * v; }
        inv[tid] = 1.0f / sqrtf(ss);
    }
    __syncthreads();

    const int tx = tid % 16, ty = tid / 16;
    float acc[4][4];
#pragma unroll
    for (int i = 0; i < 4; i++)
#pragma unroll
        for (int j = 0; j < 4; j++) acc[i][j] = 0.f;

#pragma unroll
    for (int d = 0; d < DHEAD; d++) {
        float rq[4], rc[4];
#pragma unroll
        for (int i = 0; i < 4; i++) rq[i] = qs[ty * 4 + i][d];
#pragma unroll
        for (int j = 0; j < 4; j++) rc[j] = Cs[d][tx * 4 + j];
#pragma unroll
        for (int i = 0; i < 4; i++)
#pragma unroll
            for (int j = 0; j < 4; j++)
                acc[i][j] += rq[i] * rc[j];
    }

#pragma unroll
    for (int i = 0; i < 4; i++) {
        int t = ty * 4 + i;
        float s = inv[t];
        ushort hh[4], ll[4];
#pragma unroll
        for (int j = 0; j < 4; j++) split_bf16(acc[i][j] * s, hh[j], ll[j]);
        size_t o = (size_t)(b * NTOK + n0 + t) * INNER + h * DHEAD + tx * 4;
        *reinterpret_cast<uint2*>(UH + o) = *reinterpret_cast<uint2*>(hh);
        *reinterpret_cast<uint2*>(UL + o) = *reinterpret_cast<uint2*>(ll);
    }
}

// ---------------------------------------------------------------------------
extern "C" void kernel_launch(void* const* d_in, const int* in_sizes, int n_in,
                              void* d_out, int out_size)
{
    const float* x     = (const float*)d_in[0];
    const float* W_qkv = (const float*)d_in[1];
    const float* W_o   = (const float*)d_in[2];
    const float* b_o   = (const float*)d_in[3];
    const float* gamma = (const float*)d_in[4];
    float* out = (float*)d_out;

    static bool init = false;
    static __nv_bfloat16 *uh, *ul;
    if (!init) {
        init = true;
        cudaGetSymbolAddress((void**)&uh, g_uh);
        cudaGetSymbolAddress((void**)&ul, g_ul);
        cudaFuncSetAttribute(kernelA2,
                             cudaFuncAttributeMaxDynamicSharedMemorySize, GEMM_SMEM2);
        cudaFuncSetAttribute(kernelT,
                             cudaFuncAttributeMaxDynamicSharedMemorySize, GEMM_SMEM2);
        cudaFuncSetAttribute(kernelO,
                             cudaFuncAttributeMaxDynamicSharedMemorySize, GEMM_SMEM2);
    }

    // 1) packs: x (row + transposed), Wq, Wv, Wo
    pack_stage1<<<27648, 256>>>(x, W_qkv, W_o);

    // 2) G = x^T x (full, 128 4x-long blocks first) + q = x @ Wq (512 blocks)
    kernelA2<<<640, 256, GEMM_SMEM2>>>();

    // 3) T = G @ Wv per batch
    kernelT<<<128, 256, GEMM_SMEM2>>>();

    // 4) kv = Wk^T T per (b,h), normalize, fold gamma^2 -> C
    kv_finalize_kernel<<<BATCH * HEADS, 256>>>(W_qkv, gamma);

    // 5) u = (q/||q||) @ C  (emits bf16 h/l)
    apply_kernel<<<dim3(BATCH * HEADS, NTOK / 64), 256>>>(uh, ul);

    // 6) out = u @ W_o + b_o
    kernelO<<<dim3(8, 64), 256, GEMM_SMEM2>>>(out, b_o);
}

// round 17
// speedup vs baseline: 1.2304x; 1.2304x over previous
#include <cuda_runtime.h>
#include <cuda_bf16.h>
#include <math.h>
#include <stdint.h>

#define DIM     1024
#define HEADS   16
#define DHEAD   64
#define INNER   1024
#define BATCH   4
#define NTOK    4096
#define MTOT    (BATCH * NTOK)      // 16384
#define QKVN    (3 * INNER)         // 3072
#define KSPL    8                   // finalize K-splits

// ---------------------------------------------------------------------------
// Scratch (device globals; no runtime allocation allowed)
// ---------------------------------------------------------------------------
__device__ float g_q[(size_t)MTOT * INNER];
__device__ float g_T[(size_t)BATCH * DIM * INNER];
__device__ float g_C[(size_t)BATCH * HEADS * DHEAD * DHEAD];
__device__ float g_part[(size_t)KSPL * BATCH * HEADS * DHEAD * DHEAD];  // 8 MB

__device__ __nv_bfloat16 g_xh[(size_t)MTOT * DIM];
__device__ __nv_bfloat16 g_xl[(size_t)MTOT * DIM];
__device__ __nv_bfloat16 g_xth[(size_t)BATCH * DIM * NTOK];
__device__ __nv_bfloat16 g_xtl[(size_t)BATCH * DIM * NTOK];
__device__ __nv_bfloat16 g_uh[(size_t)MTOT * DIM];
__device__ __nv_bfloat16 g_ul[(size_t)MTOT * DIM];
__device__ __nv_bfloat16 g_wqh[(size_t)INNER * DIM];
__device__ __nv_bfloat16 g_wql[(size_t)INNER * DIM];
__device__ __nv_bfloat16 g_wvh[(size_t)INNER * DIM];
__device__ __nv_bfloat16 g_wvl[(size_t)INNER * DIM];
__device__ __nv_bfloat16 g_woh[(size_t)INNER * DIM];
__device__ __nv_bfloat16 g_wol[(size_t)INNER * DIM];
__device__ __nv_bfloat16 g_Gh[(size_t)BATCH * DIM * DIM];
__device__ __nv_bfloat16 g_Gl[(size_t)BATCH * DIM * DIM];

// ---------------------------------------------------------------------------
// helpers
// ---------------------------------------------------------------------------
__device__ __forceinline__ uint32_t smem_u32(const void* p) {
    uint32_t a;
    asm("{ .reg .u64 t; cvta.to.shared.u64 t, %1; cvt.u32.u64 %0, t; }"
        : "=r"(a) : "l"(p));
    return a;
}
__device__ __forceinline__ void cp_async16(uint32_t dst, const void* src) {
    asm volatile("cp.async.cg.shared.global [%0], [%1], 16;"
                 :: "r"(dst), "l"(src) : "memory");
}
__device__ __forceinline__ void cp_commit() {
    asm volatile("cp.async.commit_group;" ::: "memory");
}
template <int N>
__device__ __forceinline__ void cp_wait() {
    asm volatile("cp.async.wait_group %0;" :: "n"(N) : "memory");
}
__device__ __forceinline__ void ldm_x4(uint32_t& r0, uint32_t& r1,
                                       uint32_t& r2, uint32_t& r3, uint32_t a) {
    asm volatile("ldmatrix.sync.aligned.m8n8.x4.shared.b16 {%0,%1,%2,%3}, [%4];"
                 : "=r"(r0), "=r"(r1), "=r"(r2), "=r"(r3) : "r"(a));
}
__device__ __forceinline__ void mma_bf16(float& c0, float& c1, float& c2, float& c3,
                                         uint32_t a0, uint32_t a1, uint32_t a2, uint32_t a3,
                                         uint32_t b0, uint32_t b1) {
    asm volatile(
        "mma.sync.aligned.m16n8k16.row.col.f32.bf16.bf16.f32 "
        "{%0,%1,%2,%3}, {%4,%5,%6,%7}, {%8,%9}, {%0,%1,%2,%3};"
        : "+f"(c0), "+f"(c1), "+f"(c2), "+f"(c3)
        : "r"(a0), "r"(a1), "r"(a2), "r"(a3), "r"(b0), "r"(b1));
}
__device__ __forceinline__ void split_bf16(float f, ushort& h, ushort& l) {
    __nv_bfloat16 hi = __float2bfloat16(f);
    __nv_bfloat16 lo = __float2bfloat16(f - __bfloat162float(hi));
    h = __bfloat16_as_ushort(hi);
    l = __bfloat16_as_ushort(lo);
}

// ---------------------------------------------------------------------------
// GEMM (R13 config): CTA tile 128x128, BK=32, 8 warps (4m x 2n), 2 CTAs/SM.
// ---------------------------------------------------------------------------
#define BKC      32
#define ROWB     80
#define OPSZ     (128 * ROWB)
#define BUFSZ    (4 * OPSZ)
#define GEMM_SMEM (2 * BUFSZ)

#define GEMM_MAINLOOP(Ah_, Al_, Bth_, Btl_, K_)                                \
    const uint32_t sb = smem_u32(smem);                                        \
    const int tid = threadIdx.x;                                               \
    const int lane = tid & 31;                                                 \
    const int wid = tid >> 5;                                                  \
    const int wm = wid & 3;                                                    \
    const int wn = wid >> 2;                                                   \
    const int g = tid >> 6;                                                    \
    const int lt = tid & 63;                                                   \
    const __nv_bfloat16* opsrc;                                                \
    if (g == 0)      opsrc = (Ah_)  + (size_t)mtile * 128 * (K_);              \
    else if (g == 1) opsrc = (Al_)  + (size_t)mtile * 128 * (K_);              \
    else if (g == 2) opsrc = (Bth_) + (size_t)ntile * 128 * (K_);              \
    else             opsrc = (Btl_) + (size_t)ntile * 128 * (K_);              \
    const int nchunks = (K_) / BKC;                                            \
    auto issue_chunk = [&](int c, int buf) {                                   \
        const uint32_t dbase = sb + buf * BUFSZ + g * OPSZ;                    \
        _Pragma("unroll")                                                      \
        for (int i = 0; i < 8; i++) {                                          \
            int idx = lt + 64 * i;                                             \
            int row = idx >> 2;                                                \
            int seg = idx & 3;                                                 \
            cp_async16(dbase + row * ROWB + seg * 16,                          \
                       opsrc + (size_t)row * (K_) + c * BKC + seg * 8);        \
        }                                                                      \
        cp_commit();                                                           \
    };                                                                         \
    float acc[2][8][4];                                                        \
    _Pragma("unroll")                                                          \
    for (int im = 0; im < 2; im++)                                             \
        _Pragma("unroll")                                                      \
        for (int jn = 0; jn < 8; jn++)                                         \
            _Pragma("unroll")                                                  \
            for (int r = 0; r < 4; r++) acc[im][jn][r] = 0.f;                  \
    const int at_tile = lane >> 3;                                             \
    const int a_row = (at_tile & 1) * 8 + (lane & 7);                          \
    const int a_cadd = (at_tile >> 1) * 16;                                    \
    const int b_row = ((at_tile >> 1) * 8) + (lane & 7);                       \
    const int b_cadd = (at_tile & 1) * 16;                                     \
    issue_chunk(0, 0);                                                         \
    for (int c = 0; c < nchunks; c++) {                                        \
        const int buf = c & 1;                                                 \
        cp_wait<0>();                                                          \
        __syncthreads();                                                       \
        if (c + 1 < nchunks) issue_chunk(c + 1, buf ^ 1);                      \
        const uint32_t base = sb + buf * BUFSZ;                                \
        _Pragma("unroll")                                                      \
        for (int kk = 0; kk < 2; kk++) {                                       \
            const int kb = kk * 32;                                            \
            uint32_t ah[2][4], al[2][4];                                       \
            _Pragma("unroll")                                                  \
            for (int im = 0; im < 2; im++) {                                   \
                uint32_t aoff = (uint32_t)(wm * 32 + im * 16 + a_row) * ROWB + kb + a_cadd; \
                ldm_x4(ah[im][0], ah[im][1], ah[im][2], ah[im][3], base + 0 * OPSZ + aoff); \
                ldm_x4(al[im][0], al[im][1], al[im][2], al[im][3], base + 1 * OPSZ + aoff); \
            }                                                                  \
            _Pragma("unroll")                                                  \
            for (int p = 0; p < 4; p++) {                                      \
                uint32_t bh4[4], bl4[4];                                       \
                uint32_t boff = (uint32_t)(wn * 64 + p * 16 + b_row) * ROWB + kb + b_cadd; \
                ldm_x4(bh4[0], bh4[1], bh4[2], bh4[3], base + 2 * OPSZ + boff);\
                ldm_x4(bl4[0], bl4[1], bl4[2], bl4[3], base + 3 * OPSZ + boff);\
                _Pragma("unroll")                                              \
                for (int im = 0; im < 2; im++) {                               \
                    _Pragma("unroll")                                          \
                    for (int q2 = 0; q2 < 2; q2++) {                           \
                        const int jn = p * 2 + q2;                             \
                        const int q = q2 * 2;                                  \
                        float* cc = acc[im][jn];                               \
                        mma_bf16(cc[0], cc[1], cc[2], cc[3],                   \
                                 ah[im][0], ah[im][1], ah[im][2], ah[im][3],   \
                                 bh4[q], bh4[q + 1]);                          \
                        mma_bf16(cc[0], cc[1], cc[2], cc[3],                   \
                                 ah[im][0], ah[im][1], ah[im][2], ah[im][3],   \
                                 bl4[q], bl4[q + 1]);                          \
                        mma_bf16(cc[0], cc[1], cc[2], cc[3],                   \
                                 al[im][0], al[im][1], al[im][2], al[im][3],   \
                                 bh4[q], bh4[q + 1]);                          \
                    }                                                          \
                }                                                              \
            }                                                                  \
        }                                                                      \
    }

__device__ __forceinline__ void gemm_body(
    char* smem, int mtile, int ntile,
    const __nv_bfloat16* __restrict__ Ah, const __nv_bfloat16* __restrict__ Al,
    const __nv_bfloat16* __restrict__ Bth, const __nv_bfloat16* __restrict__ Btl,
    float* __restrict__ C, const float* __restrict__ bias, int N, int K)
{
    GEMM_MAINLOOP(Ah, Al, Bth, Btl, K)
    const int m0 = mtile * 128 + wm * 32;
    const int n0 = ntile * 128 + wn * 64;
#pragma unroll
    for (int im = 0; im < 2; im++) {
#pragma unroll
        for (int jn = 0; jn < 8; jn++) {
            const int row = m0 + im * 16 + (lane >> 2);
            const int col = n0 + jn * 8 + (lane & 3) * 2;
            float b0 = bias ? bias[col] : 0.f;
            float b1 = bias ? bias[col + 1] : 0.f;
            float2 v0 = {acc[im][jn][0] + b0, acc[im][jn][1] + b1};
            float2 v1 = {acc[im][jn][2] + b0, acc[im][jn][3] + b1};
            *reinterpret_cast<float2*>(C + (size_t)row * N + col) = v0;
            *reinterpret_cast<float2*>(C + (size_t)(row + 8) * N + col) = v1;
        }
    }
}

__device__ __forceinline__ void gemm_sym_body(char* smem, int batch, int mtile, int ntile)
{
    const __nv_bfloat16* Abase = g_xth + (size_t)batch * DIM * NTOK;
    const __nv_bfloat16* Albase = g_xtl + (size_t)batch * DIM * NTOK;
    GEMM_MAINLOOP(Abase, Albase, Abase, Albase, NTOK)
    const int m0 = mtile * 128 + wm * 32;
    const int n0 = ntile * 128 + wn * 64;
    __nv_bfloat16* GH = g_Gh + (size_t)batch * DIM * DIM;
    __nv_bfloat16* GL = g_Gl + (size_t)batch * DIM * DIM;
    const bool mir = (mtile != ntile);
#pragma unroll
    for (int im = 0; im < 2; im++) {
#pragma unroll
        for (int jn = 0; jn < 8; jn++) {
            const int row = m0 + im * 16 + (lane >> 2);
            const int col = n0 + jn * 8 + (lane & 3) * 2;
            ushort h0, l0, h1, l1, h2, l2, h3, l3;
            split_bf16(acc[im][jn][0], h0, l0);
            split_bf16(acc[im][jn][1], h1, l1);
            split_bf16(acc[im][jn][2], h2, l2);
            split_bf16(acc[im][jn][3], h3, l3);
            *reinterpret_cast<uint32_t*>(GH + (size_t)row * DIM + col) =
                (uint32_t)h0 | ((uint32_t)h1 << 16);
            *reinterpret_cast<uint32_t*>(GL + (size_t)row * DIM + col) =
                (uint32_t)l0 | ((uint32_t)l1 << 16);
            *reinterpret_cast<uint32_t*>(GH + (size_t)(row + 8) * DIM + col) =
                (uint32_t)h2 | ((uint32_t)h3 << 16);
            *reinterpret_cast<uint32_t*>(GL + (size_t)(row + 8) * DIM + col) =
                (uint32_t)l2 | ((uint32_t)l3 << 16);
            if (mir) {
                GH[(size_t)col * DIM + row]           = __ushort_as_bfloat16(h0);
                GH[(size_t)(col + 1) * DIM + row]     = __ushort_as_bfloat16(h1);
                GH[(size_t)col * DIM + row + 8]       = __ushort_as_bfloat16(h2);
                GH[(size_t)(col + 1) * DIM + row + 8] = __ushort_as_bfloat16(h3);
                GL[(size_t)col * DIM + row]           = __ushort_as_bfloat16(l0);
                GL[(size_t)(col + 1) * DIM + row]     = __ushort_as_bfloat16(l1);
                GL[(size_t)col * DIM + row + 8]       = __ushort_as_bfloat16(l2);
                GL[(size_t)(col + 1) * DIM + row + 8] = __ushort_as_bfloat16(l3);
            }
        }
    }
}

__global__ __launch_bounds__(256, 2) void gemm_bf16x3_kernel(
    const __nv_bfloat16* __restrict__ Ah, const __nv_bfloat16* __restrict__ Al,
    const __nv_bfloat16* __restrict__ Bth, const __nv_bfloat16* __restrict__ Btl,
    float* __restrict__ C, const float* __restrict__ bias, int N, int K)
{
    extern __shared__ char smem[];
    gemm_body(smem, blockIdx.y, blockIdx.x, Ah, Al, Bth, Btl, C, bias, N, K);
}

// Kernel A: G lower tiles (144, 4x work, first) + q-GEMM (1024)
__global__ __launch_bounds__(256, 2) void kernelA()
{
    extern __shared__ char smem[];
    const int bx = blockIdx.x;
    if (bx < 144) {
        const int batch = bx / 36, t = bx % 36;
        int mt = 0;
        while ((mt + 1) * (mt + 2) / 2 <= t) mt++;
        const int nt = t - mt * (mt + 1) / 2;
        gemm_sym_body(smem, batch, mt, nt);
    } else {
        const int i = bx - 144;
        gemm_body(smem, i >> 3, i & 7, g_xh, g_xl, g_wqh, g_wql,
                  g_q, nullptr, INNER, DIM);
    }
}

// ---------------------------------------------------------------------------
// Stage-1 packs
// ---------------------------------------------------------------------------
__device__ __forceinline__ void packbt_g(
    float (*tile)[33], const float* __restrict__ W, int ldW, int col0,
    __nv_bfloat16* __restrict__ H, __nv_bfloat16* __restrict__ L,
    size_t outbase, int Kout, int kt, int nt)
{
    const int k0 = kt * 32, n0 = nt * 32;
    const int x = threadIdx.x & 31, y = threadIdx.x >> 5;

#pragma unroll
    for (int r = 0; r < 4; r++) {
        int row = y + r * 8;
        tile[row][x] = W[(size_t)(k0 + row) * ldW + col0 + n0 + x];
    }
    __syncthreads();
#pragma unroll
    for (int r = 0; r < 4; r++) {
        int n = y + r * 8;
        float f = tile[x][n];
        ushort h, l;
        split_bf16(f, h, l);
        size_t o = outbase + (size_t)(n0 + n) * Kout + k0 + x;
        H[o] = __ushort_as_bfloat16(h);
        L[o] = __ushort_as_bfloat16(l);
    }
}

__global__ __launch_bounds__(256) void pack_stage1(
    const float* __restrict__ x, const float* __restrict__ W_qkv,
    const float* __restrict__ W_o)
{
    __shared__ float tile[32][33];
    const int bx = blockIdx.x;
    if (bx < 8192) {
        const size_t e0 = ((size_t)bx * 256 + threadIdx.x) * 8;
        float4 v0 = *reinterpret_cast<const float4*>(x + e0);
        float4 v1 = *reinterpret_cast<const float4*>(x + e0 + 4);
        float f[8] = {v0.x, v0.y, v0.z, v0.w, v1.x, v1.y, v1.z, v1.w};
        ushort h[8], l[8];
#pragma unroll
        for (int i = 0; i < 8; i++) split_bf16(f[i], h[i], l[i]);
        *reinterpret_cast<uint4*>(g_xh + e0) = *reinterpret_cast<uint4*>(h);
        *reinterpret_cast<uint4*>(g_xl + e0) = *reinterpret_cast<uint4*>(l);
    } else if (bx < 24576) {
        const int i = bx - 8192;
        const int batch = i >> 12;
        const int t = i & 4095;
        const int kt = t & 127, nt = t >> 7;
        packbt_g(tile, x + (size_t)batch * NTOK * DIM, DIM, 0,
                 g_xth, g_xtl, (size_t)batch * DIM * NTOK, NTOK, kt, nt);
    } else if (bx < 25600) {
        const int t = bx - 24576;
        packbt_g(tile, W_qkv, QKVN, 0, g_wqh, g_wql, 0, DIM, t & 31, t >> 5);
    } else if (bx < 26624) {
        const int t = bx - 25600;
        packbt_g(tile, W_qkv, QKVN, 2 * INNER, g_wvh, g_wvl, 0, DIM, t & 31, t >> 5);
    } else {
        const int t = bx - 26624;
        packbt_g(tile, W_o, INNER, 0, g_woh, g_wol, 0, DIM, t & 31, t >> 5);
    }
}

// ---------------------------------------------------------------------------
// finalize split-K: partial kv_bh over K slice of 128
// ---------------------------------------------------------------------------
#define FCH 16

__global__ __launch_bounds__(256) void kv_partial2_kernel(const float* __restrict__ W_qkv)
{
    const int bh = blockIdx.x;       // 64
    const int ks = blockIdx.y;       // 8
    const int b = bh >> 4, h = bh & 15;
    const int k0 = ks * (DIM / KSPL);     // 128-row slice

    __shared__ float wks[2][FCH][DHEAD];
    __shared__ float ts[2][FCH][DHEAD];

    const int tid = threadIdx.x;
    const int tx = tid % 16, ty = tid / 16;
    const int lr = tid >> 4, lc = (tid * 4) & 63;

    const uint32_t wk_a[2] = {smem_u32(&wks[0][lr][lc]), smem_u32(&wks[1][lr][lc])};
    const uint32_t ts_a[2] = {smem_u32(&ts[0][lr][lc]), smem_u32(&ts[1][lr][lc])};

    auto issue = [&](int s, int buf) {
        const int krow = k0 + s * FCH + lr;
        const float* wp = W_qkv + (size_t)krow * QKVN + INNER + h * DHEAD + lc;
        const float* tp = g_T + ((size_t)b * DIM + krow) * INNER + h * DHEAD + lc;
        cp_async16(wk_a[buf], wp);
        cp_async16(ts_a[buf], tp);
        cp_commit();
    };

    float acc[4][4];
#pragma unroll
    for (int i = 0; i < 4; i++)
#pragma unroll
        for (int j = 0; j < 4; j++) acc[i][j] = 0.f;

    const int nst = (DIM / KSPL) / FCH;   // 8
    issue(0, 0);
    for (int s = 0; s < nst; s++) {
        const int buf = s & 1;
        if (s + 1 < nst) { issue(s + 1, buf ^ 1); cp_wait<1>(); }
        else             { cp_wait<0>(); }
        __syncthreads();
#pragma unroll
        for (int nn = 0; nn < FCH; nn++) {
            float rk[4], rv[4];
#pragma unroll
            for (int i = 0; i < 4; i++) rk[i] = wks[buf][nn][ty * 4 + i];
#pragma unroll
            for (int j = 0; j < 4; j++) rv[j] = ts[buf][nn][tx * 4 + j];
#pragma unroll
            for (int i = 0; i < 4; i++)
#pragma unroll
                for (int j = 0; j < 4; j++)
                    acc[i][j] += rk[i] * rv[j];
        }
        __syncthreads();
    }

    float* out = g_part + ((size_t)ks * BATCH * HEADS + bh) * (DHEAD * DHEAD);
#pragma unroll
    for (int i = 0; i < 4; i++)
#pragma unroll
        for (int j = 0; j < 4; j++)
            out[(ty * 4 + i) * DHEAD + tx * 4 + j] = acc[i][j];
}

// reduce 8 partials, row-normalize * gamma^2 -> C. grid 64, 256 thr.
__global__ __launch_bounds__(256) void kv_reduce_kernel(const float* __restrict__ gamma)
{
    const int bh = blockIdx.x;
    const int h = bh & 15;
    const int tid = threadIdx.x;
    const int tx = tid % 16, ty = tid / 16;   // ty=row/4 group, tx=col/4 group

    __shared__ float red[64][17];
    __shared__ float inv[64];

    float acc[4][4];
#pragma unroll
    for (int i = 0; i < 4; i++)
#pragma unroll
        for (int j = 0; j < 4; j++) acc[i][j] = 0.f;

#pragma unroll
    for (int s = 0; s < KSPL; s++) {
        const float* p = g_part + ((size_t)s * BATCH * HEADS + bh) * (DHEAD * DHEAD);
#pragma unroll
        for (int i = 0; i < 4; i++) {
            float4 v = *reinterpret_cast<const float4*>(p + (ty * 4 + i) * DHEAD + tx * 4);
            acc[i][0] += v.x; acc[i][1] += v.y; acc[i][2] += v.z; acc[i][3] += v.w;
        }
    }

#pragma unroll
    for (int i = 0; i < 4; i++)
        red[ty * 4 + i][tx] = acc[i][0] * acc[i][0] + acc[i][1] * acc[i][1] +
                              acc[i][2] * acc[i][2] + acc[i][3] * acc[i][3];
    __syncthreads();
    if (tid < 64) {
        float s = 0.f;
#pragma unroll
        for (int t = 0; t < 16; t++) s += red[tid][t];
        const float gm = gamma[h];
        inv[tid] = gm * gm / sqrtf(s);
    }
    __syncthreads();

    float* out = g_C + (size_t)bh * DHEAD * DHEAD;
#pragma unroll
    for (int i = 0; i < 4; i++) {
        const float sc = inv[ty * 4 + i];
        float4 v = {acc[i][0] * sc, acc[i][1] * sc, acc[i][2] * sc, acc[i][3] * sc};
        *reinterpret_cast<float4*>(out + (ty * 4 + i) * DHEAD + tx * 4) = v;
    }
}

// ---------------------------------------------------------------------------
// apply: u = (q @ C) / ||q||, emits bf16 hi/lo
// ---------------------------------------------------------------------------
#define QPAD 68

__global__ __launch_bounds__(256) void apply_kernel(
    __nv_bfloat16* __restrict__ UH, __nv_bfloat16* __restrict__ UL)
{
    const int bh = blockIdx.x;
    const int chunk = blockIdx.y;
    const int b = bh / HEADS, h = bh % HEADS;

    __shared__ float Cs[DHEAD][DHEAD];
    __shared__ float qs[64][QPAD];
    __shared__ float inv[64];

    const int tid = threadIdx.x;
    const int n0 = chunk * 64;

#pragma unroll
    for (int i = tid * 4; i < DHEAD * DHEAD; i += 1024)
        *reinterpret_cast<float4*>(&Cs[0][0] + i) =
            *reinterpret_cast<const float4*>(g_C + (size_t)bh * DHEAD * DHEAD + i);

#pragma unroll
    for (int i = tid * 4; i < 64 * DHEAD; i += 1024) {
        int t = i / DHEAD, d = i % DHEAD;
        *reinterpret_cast<float4*>(&qs[t][d]) =
            *reinterpret_cast<const float4*>(g_q + (size_t)(b * NTOK + n0 + t) * INNER + h * DHEAD + d);
    }
    __syncthreads();

    if (tid < 64) {
        float ss = 0.f;
#pragma unroll
        for (int d = 0; d < DHEAD; d++) { float v = qs[tid][d]; ss += v * v; }
        inv[tid] = 1.0f / sqrtf(ss);
    }
    __syncthreads();

    const int tx = tid % 16, ty = tid / 16;
    float acc[4][4];
#pragma unroll
    for (int i = 0; i < 4; i++)
#pragma unroll
        for (int j = 0; j < 4; j++) acc[i][j] = 0.f;

#pragma unroll
    for (int d = 0; d < DHEAD; d++) {
        float rq[4], rc[4];
#pragma unroll
        for (int i = 0; i < 4; i++) rq[i] = qs[ty * 4 + i][d];
#pragma unroll
        for (int j = 0; j < 4; j++) rc[j] = Cs[d][tx * 4 + j];
#pragma unroll
        for (int i = 0; i < 4; i++)
#pragma unroll
            for (int j = 0; j < 4; j++)
                acc[i][j] += rq[i] * rc[j];
    }

#pragma unroll
    for (int i = 0; i < 4; i++) {
        int t = ty * 4 + i;
        float s = inv[t];
        ushort hh[4], ll[4];
#pragma unroll
        for (int j = 0; j < 4; j++) split_bf16(acc[i][j] * s, hh[j], ll[j]);
        size_t o = (size_t)(b * NTOK + n0 + t) * INNER + h * DHEAD + tx * 4;
        *reinterpret_cast<uint2*>(UH + o) = *reinterpret_cast<uint2*>(hh);
        *reinterpret_cast<uint2*>(UL + o) = *reinterpret_cast<uint2*>(ll);
    }
}

// ---------------------------------------------------------------------------
extern "C" void kernel_launch(void* const* d_in, const int* in_sizes, int n_in,
                              void* d_out, int out_size)
{
    const float* x     = (const float*)d_in[0];
    const float* W_qkv = (const float*)d_in[1];
    const float* W_o   = (const float*)d_in[2];
    const float* b_o   = (const float*)d_in[3];
    const float* gamma = (const float*)d_in[4];
    float* out = (float*)d_out;

    static float* T_p = nullptr;
    static __nv_bfloat16 *uh, *ul, *woh, *wol, *wvh, *wvl, *Gh, *Gl;
    if (!T_p) {
        cudaGetSymbolAddress((void**)&T_p, g_T);
        cudaGetSymbolAddress((void**)&uh, g_uh);
        cudaGetSymbolAddress((void**)&ul, g_ul);
        cudaGetSymbolAddress((void**)&woh, g_woh);
        cudaGetSymbolAddress((void**)&wol, g_wol);
        cudaGetSymbolAddress((void**)&wvh, g_wvh);
        cudaGetSymbolAddress((void**)&wvl, g_wvl);
        cudaGetSymbolAddress((void**)&Gh, g_Gh);
        cudaGetSymbolAddress((void**)&Gl, g_Gl);
        cudaFuncSetAttribute(gemm_bf16x3_kernel,
                             cudaFuncAttributeMaxDynamicSharedMemorySize, GEMM_SMEM);
        cudaFuncSetAttribute(kernelA,
                             cudaFuncAttributeMaxDynamicSharedMemorySize, GEMM_SMEM);
    }

    // 1) packs: x (row + transposed), Wq, Wv, Wo
    pack_stage1<<<27648, 256>>>(x, W_qkv, W_o);

    // 2) G = x^T x (lower tiles first) + q = x @ Wq
    kernelA<<<1168, 256, GEMM_SMEM>>>();

    // 3) T = G @ Wv
    gemm_bf16x3_kernel<<<dim3(8, 32), 256, GEMM_SMEM>>>(
        Gh, Gl, wvh, wvl, T_p, nullptr, INNER, DIM);

    // 4) kv partials (split-K, 512 blocks) + reduce/normalize
    kv_partial2_kernel<<<dim3(BATCH * HEADS, KSPL), 256>>>(W_qkv);
    kv_reduce_kernel<<<BATCH * HEADS, 256>>>(gamma);

    // 5) u = (q/||q||) @ C
    apply_kernel<<<dim3(BATCH * HEADS, NTOK / 64), 256>>>(uh, ul);

    // 6) out = u @ W_o + b_o
    gemm_bf16x3_kernel<<<dim3(8, 128), 256, GEMM_SMEM>>>(
        uh, ul, woh, wol, out, b_o, INNER, DIM);
}